// round 10
// baseline (speedup 1.0000x reference)
#include <cuda_runtime.h>
#include <cuda_bf16.h>
#include <cstdint>
#include <math.h>

// Problem constants
#define BATCH 4
#define SEQ   2048
#define SP    2064            // padded sequence (pad = 16)
#define DIM   1024
#define NH    16
#define QL    16
#define VL    64
#define NTOT  3072            // interleaved: col 2p = value, col 2p+1 = gate
#define MROWS (BATCH*SEQ)     // 8192

// -------- device scratch --------
__device__ float g_Wt[(size_t)NTOT * DIM];      // transposed tf32 weights [n][k]
__device__ float g_x32[(size_t)MROWS * DIM];    // tf32-converted x
__device__ float g_ball[NTOT];
__device__ float g_q[(size_t)BATCH * NH * SP * QL];   // [bh][s][d]  (raw fp32)
__device__ float g_k[(size_t)BATCH * NH * SP * QL];   // [bh][s][d]  (raw fp32)
__device__ float g_vt[(size_t)BATCH * NH * VL * SP];  // [bh][d][s]  (tf32-rounded)

__device__ __forceinline__ float to_tf32(float x) {
    uint32_t u;
    asm("cvt.rna.tf32.f32 %0, %1;" : "=r"(u) : "f"(x));
    return __uint_as_float(u);
}
__device__ __forceinline__ float sigm(float x) { return 1.f / (1.f + __expf(-x)); }

__device__ __forceinline__ uint32_t smem_u32(const void* p) {
    uint32_t a;
    asm("{ .reg .u64 t; cvta.to.shared.u64 t, %1; cvt.u32.u64 %0, t; }" : "=r"(a) : "l"(p));
    return a;
}
__device__ __forceinline__ void cpa16(uint32_t dst, const float* src, bool ok) {
    int sz = ok ? 16 : 0;
    asm volatile("cp.async.cg.shared.global [%0], [%1], 16, %2;"
                 :: "r"(dst), "l"(src), "r"(sz));
}
__device__ __forceinline__ void cpa16u(uint32_t dst, const float* src) {
    asm volatile("cp.async.cg.shared.global [%0], [%1], 16;"
                 :: "r"(dst), "l"(src));
}
#define CPA_COMMIT() asm volatile("cp.async.commit_group;" ::: "memory")

__device__ __forceinline__ void mma16n8k8(float* d, const float* a, const float* b) {
    asm volatile("mma.sync.aligned.m16n8k8.row.col.f32.tf32.tf32.f32 "
        "{%0,%1,%2,%3}, {%4,%5,%6,%7}, {%8,%9}, {%0,%1,%2,%3};"
        : "+f"(d[0]), "+f"(d[1]), "+f"(d[2]), "+f"(d[3])
        : "r"(__float_as_uint(a[0])), "r"(__float_as_uint(a[1])),
          "r"(__float_as_uint(a[2])), "r"(__float_as_uint(a[3])),
          "r"(__float_as_uint(b[0])), "r"(__float_as_uint(b[1])));
}

// ======================= prep kernels =======================
__global__ void fill_bias(const float* __restrict__ bq,  const float* __restrict__ bqc,
                          const float* __restrict__ bk,  const float* __restrict__ bkc,
                          const float* __restrict__ bv,  const float* __restrict__ bvc) {
    int idx = blockIdx.x * blockDim.x + threadIdx.x;
    if (idx >= NTOT) return;
    int p = idx >> 1;
    bool gate = (idx & 1);
    float bb;
    if (p < 256)      bb = gate ? bqc[p]      : bq[p];
    else if (p < 512) bb = gate ? bkc[p-256]  : bk[p-256];
    else              bb = gate ? bvc[p-512]  : bv[p-512];
    g_ball[idx] = bb;
}

// padded key rows (s in [2048,2064)) bias-only constants for k, v(transposed)
__global__ void pad_fill() {
    int idx = blockIdx.x * blockDim.x + threadIdx.x;
    const int total = BATCH * 16 * 1280;
    if (idx >= total) return;
    int c = 256 + (idx % 1280);
    int t = idx / 1280;
    int sp = 2048 + (t & 15);
    int b = t >> 4;
    float val = g_ball[2*c] * sigm(g_ball[2*c + 1]);
    if (c < 512) {
        int l = c - 256; int h = l >> 4, d = l & 15;
        g_k[((size_t)(b*NH + h) * SP + sp) * QL + d] = val;
    } else {
        int l = c - 512; int h = l >> 6, d = l & 63;
        g_vt[((size_t)(b*NH + h) * VL + d) * SP + sp] = to_tf32(val);
    }
}

__device__ __forceinline__ float fetch_w(int k, int n,
        const float* Wq, const float* Wqc, const float* Wk, const float* Wkc,
        const float* Wv, const float* Wvc) {
    int p = n >> 1;
    bool gate = (n & 1);
    if (p < 256)      return gate ? Wqc[k*256 + p]        : Wq[k*256 + p];
    if (p < 512)      { int l = p-256; return gate ? Wkc[k*256 + l]  : Wk[k*256 + l]; }
    { int l = p-512; return gate ? Wvc[k*1024 + l] : Wv[k*1024 + l]; }
}

// transpose W into g_Wt[n][k] (tf32-converted)
__global__ void transpose_w(const float* __restrict__ Wq,  const float* __restrict__ Wqc,
                            const float* __restrict__ Wk,  const float* __restrict__ Wkc,
                            const float* __restrict__ Wv,  const float* __restrict__ Wvc) {
    __shared__ float tile[32][33];
    int n0 = blockIdx.x * 32, k0 = blockIdx.y * 32;
    int tx = threadIdx.x & 31, ty = threadIdx.x >> 5;
    #pragma unroll
    for (int r = ty; r < 32; r += 8)
        tile[tx][r] = fetch_w(k0 + r, n0 + tx, Wq, Wqc, Wk, Wkc, Wv, Wvc);
    __syncthreads();
    #pragma unroll
    for (int r = ty; r < 32; r += 8)
        g_Wt[(size_t)(n0 + r) * DIM + k0 + tx] = to_tf32(tile[r][tx]);
}

// convert x to tf32 (rna)
__global__ void xcvt(const float* __restrict__ x) {
    size_t i = ((size_t)blockIdx.x * blockDim.x + threadIdx.x) * 4;
    float4 v = *(const float4*)(x + i);
    v.x = to_tf32(v.x); v.y = to_tf32(v.y); v.z = to_tf32(v.z); v.w = to_tf32(v.w);
    *(float4*)(((float*)g_x32) + i) = v;
}

// ======================= mma.sync tf32 GEMM + CSS epilogue =======================
// C[8192,3072] = g_x32 @ g_Wt^T. CTA 128x256x16, 8 warps (2m x 4n), warp 64x64.
// 4-stage cp.async pipeline, one __syncthreads per stage.
#define GKT 64              // 1024/16 stages
#define GSTR 20             // smem row stride (floats)
#define GA_ST 2560          // A stage floats (128*20)
#define GB_ST 5120          // B stage floats (256*20)
#define GSM_B 10240         // B region offset (floats) = 4*GA_ST
#define GSM_TOT (GSM_B + 4*GB_ST)   // 30720 floats = 122880 bytes

__global__ __launch_bounds__(256, 1) void gemm_mma() {
    extern __shared__ float sm[];
    const uint32_t smb = smem_u32(sm);

    const int tid  = threadIdx.x;
    const int wid  = tid >> 5, lane = tid & 31;
    const int wm   = wid & 1,  wn   = wid >> 1;
    const int lg   = lane >> 2, lq  = lane & 3;
    const int bm   = blockIdx.y * 128;
    const int bn   = blockIdx.x * 256;

    // loader decomposition
    const int arow = tid >> 2;            // A: c = it*256+tid, it<2 -> rows 0..127
    const int aq   = (tid & 3) * 4;
    const float* Ag = g_x32 + (size_t)(bm + arow) * DIM + aq;
    const float* Bg0 = g_Wt + (size_t)(bn + arow) * DIM + aq;        // rows 0..63 per it? no:
    // B: c = it*256 + tid, it<4 -> row = c>>2 in 0..255
    // row(it) = it*64 + (tid>>2)
    // prologue: issue stages 0..2
    #pragma unroll
    for (int s = 0; s < 3; s++) {
        const int k0 = s * 16;
        const int ab = s & 3;
        #pragma unroll
        for (int it = 0; it < 2; it++) {
            int row = it * 64 + (tid >> 2);
            cpa16u(smb + (ab*GA_ST + row*GSTR + aq) * 4,
                   g_x32 + (size_t)(bm + row) * DIM + k0 + aq);
        }
        #pragma unroll
        for (int it = 0; it < 4; it++) {
            int row = it * 64 + (tid >> 2);
            cpa16u(smb + (GSM_B + ab*GB_ST + row*GSTR + aq) * 4,
                   g_Wt + (size_t)(bn + row) * DIM + k0 + aq);
        }
        CPA_COMMIT();
    }

    float acc[4][8][4];
    #pragma unroll
    for (int i = 0; i < 4; i++)
        #pragma unroll
        for (int j = 0; j < 8; j++)
            #pragma unroll
            for (int r = 0; r < 4; r++) acc[i][j][r] = 0.f;

    for (int t = 0; t < GKT; t++) {
        asm volatile("cp.async.wait_group 2;" ::: "memory");
        __syncthreads();
        // issue stage t+3 (or empty commit to keep group accounting exact)
        if (t + 3 < GKT) {
            const int k0 = (t + 3) * 16;
            const int ab = (t + 3) & 3;
            #pragma unroll
            for (int it = 0; it < 2; it++) {
                int row = it * 64 + (tid >> 2);
                cpa16u(smb + (ab*GA_ST + row*GSTR + aq) * 4,
                       g_x32 + (size_t)(bm + row) * DIM + k0 + aq);
            }
            #pragma unroll
            for (int it = 0; it < 4; it++) {
                int row = it * 64 + (tid >> 2);
                cpa16u(smb + (GSM_B + ab*GB_ST + row*GSTR + aq) * 4,
                       g_Wt + (size_t)(bn + row) * DIM + k0 + aq);
            }
        }
        CPA_COMMIT();

        const float* Ab = sm + (t & 3) * GA_ST;
        const float* Bb = sm + GSM_B + (t & 3) * GB_ST;

        #pragma unroll
        for (int ks = 0; ks < 2; ks++) {
            const int kk = ks * 8;
            float b[8][2];
            #pragma unroll
            for (int nt = 0; nt < 8; nt++) {
                int n0 = wn*64 + nt*8 + lg;
                b[nt][0] = Bb[n0*GSTR + kk + lq];
                b[nt][1] = Bb[n0*GSTR + kk + lq + 4];
            }
            #pragma unroll
            for (int mt = 0; mt < 4; mt++) {
                int r0 = wm*64 + mt*16 + lg;
                float a[4];
                a[0] = Ab[r0*GSTR + kk + lq];
                a[1] = Ab[(r0+8)*GSTR + kk + lq];
                a[2] = Ab[r0*GSTR + kk + lq + 4];
                a[3] = Ab[(r0+8)*GSTR + kk + lq + 4];
                #pragma unroll
                for (int nt = 0; nt < 8; nt++)
                    mma16n8k8(acc[mt][nt], a, b[nt]);
            }
        }
    }

    // ---- epilogue: CSS gate + scatter (c0,c1)=(value,gate) per thread ----
    #pragma unroll
    for (int mt = 0; mt < 4; mt++) {
        int mrow0 = bm + wm*64 + mt*16 + lg;
        #pragma unroll
        for (int nt = 0; nt < 8; nt++) {
            int jc = bn + wn*64 + nt*8 + 2*lq;   // packed col of c0 (even)
            float bv = g_ball[jc];
            float bg = g_ball[jc + 1];
            int p = jc >> 1;
            #pragma unroll
            for (int half = 0; half < 2; half++) {
                int m = mrow0 + 8*half;
                float val = (acc[mt][nt][2*half] + bv) * sigm(acc[mt][nt][2*half + 1] + bg);
                int b_ = m >> 11;
                int s  = m & 2047;
                if (p < 256) {
                    g_q[((size_t)(b_*NH + (p >> 4)) * SP + s) * QL + (p & 15)] = val;
                } else if (p < 512) {
                    int l = p - 256;
                    g_k[((size_t)(b_*NH + (l >> 4)) * SP + s) * QL + (l & 15)] = val;
                } else {
                    int l = p - 512;
                    g_vt[((size_t)(b_*NH + (l >> 6)) * VL + (l & 63)) * SP + s] = to_tf32(val);
                }
            }
        }
    }
}

// ======================= tensor-core flash attention =======================
// CTA: 128 q-rows, 4 warps. 32-key tiles, 3-stage cp.async pipeline.
// QK: 3-mma hi/lo compensation (~fp32 scores). PV: tf32 (V pre-rounded, P rna).
#define PSTR 36
#define KSTR 20
#define SM_Q   0                    // 128*20 = 2560
#define SM_K   2560                 // 3 bufs * 640
#define SM_V   4480                 // 3 bufs * 2304
#define SM_P   11392                // 4 warps * 1152
#define SM_TOT 16000                // floats (64000 bytes)

__global__ __launch_bounds__(128) void attn_mma(float* __restrict__ out) {
    extern __shared__ float sm[];
    const int qt = blockIdx.x, h = blockIdx.y, b = blockIdx.z;
    const int bh = b * NH + h;

    const int tid = threadIdx.x;
    const int wid = tid >> 5, lane = tid & 31;
    const int lg = lane >> 2, lq = lane & 3;

    const float* kb = g_k  + (size_t)bh * SP * QL;
    const float* vb = g_vt + (size_t)bh * VL * SP;

    const uint32_t smbase = smem_u32(sm);

    const int krow = tid >> 2, kfq = (tid & 3) * 4;
    const int NKT = (SP + 31) / 32;   // 65

    // ---- stage Q tile [128][16] ----
    {
        const float* src = g_q + ((size_t)bh * SP + qt*128 + tid) * QL;
        #pragma unroll
        for (int u = 0; u < 4; u++)
            *(float4*)&sm[SM_Q + tid*KSTR + u*4] = *(const float4*)(src + u*4);
    }

    // prologue: issue tiles 0,1
    #pragma unroll
    for (int pt = 0; pt < 2; pt++) {
        const int k0 = pt * 32;
        const int kbuf = SM_K + pt * 640, vbuf = SM_V + pt * 2304;
        {
            int gk = k0 + krow;
            bool ok = gk < SP;
            cpa16(smbase + (kbuf + krow*KSTR + kfq) * 4, kb + (size_t)(ok ? gk : 0) * QL + kfq, ok);
        }
        #pragma unroll
        for (int it = 0; it < 4; it++) {
            int chunk = it * 128 + tid;
            int d = chunk >> 3, cp = (chunk & 7) * 4;
            bool ok = (k0 + cp + 4) <= SP;
            cpa16(smbase + (vbuf + d*PSTR + cp) * 4, vb + (size_t)d * SP + (ok ? k0 + cp : 0), ok);
        }
        CPA_COMMIT();
    }
    __syncthreads();

    // Q fragments hi/lo (softmax scale 0.125 folded in before split)
    float qh[2][2][4], ql[2][2][4];
    #pragma unroll
    for (int mt = 0; mt < 2; mt++)
        #pragma unroll
        for (int kk = 0; kk < 2; kk++) {
            int r0 = wid*32 + mt*16 + lg;
            #pragma unroll
            for (int e = 0; e < 4; e++) {
                int rr = r0 + ((e & 1) ? 8 : 0);
                int cc = kk*8 + lq + ((e >= 2) ? 4 : 0);
                float qs = sm[SM_Q + rr*KSTR + cc] * 0.125f;
                float hh = to_tf32(qs);
                qh[mt][kk][e] = hh;
                ql[mt][kk][e] = to_tf32(qs - hh);
            }
        }

    float O[2][8][4];
    #pragma unroll
    for (int mt = 0; mt < 2; mt++)
        #pragma unroll
        for (int nt = 0; nt < 8; nt++)
            #pragma unroll
            for (int c = 0; c < 4; c++) O[mt][nt][c] = 0.f;
    float m_run[4], l_run[4];
    #pragma unroll
    for (int r = 0; r < 4; r++) { m_run[r] = -1e30f; l_run[r] = 0.f; }

    float* pw = sm + SM_P + wid * 1152;

    for (int kt = 0; kt < NKT; kt++) {
        const int k0 = kt * 32;
        if (kt + 1 < NKT) asm volatile("cp.async.wait_group 1;" ::: "memory");
        else              asm volatile("cp.async.wait_group 0;" ::: "memory");
        __syncthreads();
        if (kt + 2 < NKT) {
            const int k2 = (kt + 2) * 32;
            const int bi = (kt + 2) % 3;
            const int kbuf = SM_K + bi * 640, vbuf = SM_V + bi * 2304;
            {
                int gk = k2 + krow;
                bool ok = gk < SP;
                cpa16(smbase + (kbuf + krow*KSTR + kfq) * 4, kb + (size_t)(ok ? gk : 0) * QL + kfq, ok);
            }
            #pragma unroll
            for (int it = 0; it < 4; it++) {
                int chunk = it * 128 + tid;
                int d = chunk >> 3, cp = (chunk & 7) * 4;
                bool ok = (k2 + cp + 4) <= SP;
                cpa16(smbase + (vbuf + d*PSTR + cp) * 4, vb + (size_t)d * SP + (ok ? k2 + cp : 0), ok);
            }
            CPA_COMMIT();
        }

        const float* kbuf = sm + SM_K + (kt % 3) * 640;
        const float* vbuf = sm + SM_V + (kt % 3) * 2304;

        // ---- QK (3-mma compensated) ----
        float sc[2][4][4];
        #pragma unroll
        for (int mt = 0; mt < 2; mt++)
            #pragma unroll
            for (int nt = 0; nt < 4; nt++)
                #pragma unroll
                for (int c = 0; c < 4; c++) sc[mt][nt][c] = 0.f;
        #pragma unroll
        for (int kk = 0; kk < 2; kk++) {
            #pragma unroll
            for (int nt = 0; nt < 4; nt++) {
                float r0 = kbuf[(nt*8 + lg)*KSTR + kk*8 + lq];
                float r1 = kbuf[(nt*8 + lg)*KSTR + kk*8 + lq + 4];
                float h0 = to_tf32(r0), h1 = to_tf32(r1);
                float bh_[2] = { h0, h1 };
                float bl_[2] = { to_tf32(r0 - h0), to_tf32(r1 - h1) };
                #pragma unroll
                for (int mt = 0; mt < 2; mt++) {
                    mma16n8k8(sc[mt][nt], qh[mt][kk], bh_);
                    mma16n8k8(sc[mt][nt], ql[mt][kk], bh_);
                    mma16n8k8(sc[mt][nt], qh[mt][kk], bl_);
                }
            }
        }
        if (k0 + 32 > SP) {
            #pragma unroll
            for (int nt = 0; nt < 4; nt++)
                #pragma unroll
                for (int c = 0; c < 4; c++) {
                    int col = k0 + nt*8 + 2*lq + (c & 1);
                    if (col >= SP) { sc[0][nt][c] = -1e30f; sc[1][nt][c] = -1e30f; }
                }
        }

        // ---- softmax ----
        float mloc[4];
        #pragma unroll
        for (int mt = 0; mt < 2; mt++) {
            float v0 = fmaxf(fmaxf(sc[mt][0][0], sc[mt][0][1]), fmaxf(sc[mt][1][0], sc[mt][1][1]));
            v0 = fmaxf(v0, fmaxf(fmaxf(sc[mt][2][0], sc[mt][2][1]), fmaxf(sc[mt][3][0], sc[mt][3][1])));
            float v1 = fmaxf(fmaxf(sc[mt][0][2], sc[mt][0][3]), fmaxf(sc[mt][1][2], sc[mt][1][3]));
            v1 = fmaxf(v1, fmaxf(fmaxf(sc[mt][2][2], sc[mt][2][3]), fmaxf(sc[mt][3][2], sc[mt][3][3])));
            mloc[2*mt]   = v0;
            mloc[2*mt+1] = v1;
        }
        #pragma unroll
        for (int r = 0; r < 4; r++) {
            float v = mloc[r];
            v = fmaxf(v, __shfl_xor_sync(0xffffffffu, v, 1));
            v = fmaxf(v, __shfl_xor_sync(0xffffffffu, v, 2));
            mloc[r] = v;
        }
        float alpha[4];
        #pragma unroll
        for (int r = 0; r < 4; r++) {
            float mn = fmaxf(m_run[r], mloc[r]);
            alpha[r] = __expf(m_run[r] - mn);
            m_run[r] = mn;
            l_run[r] *= alpha[r];
        }
        float lsum[4] = {0.f, 0.f, 0.f, 0.f};
        #pragma unroll
        for (int mt = 0; mt < 2; mt++)
            #pragma unroll
            for (int nt = 0; nt < 4; nt++) {
                float p0 = __expf(sc[mt][nt][0] - m_run[2*mt]);
                float p1 = __expf(sc[mt][nt][1] - m_run[2*mt]);
                float p2 = __expf(sc[mt][nt][2] - m_run[2*mt+1]);
                float p3 = __expf(sc[mt][nt][3] - m_run[2*mt+1]);
                lsum[2*mt]   += p0 + p1;
                lsum[2*mt+1] += p2 + p3;
                *(float2*)&pw[(mt*16 + lg)*PSTR     + nt*8 + 2*lq] = make_float2(to_tf32(p0), to_tf32(p1));
                *(float2*)&pw[(mt*16 + lg + 8)*PSTR + nt*8 + 2*lq] = make_float2(to_tf32(p2), to_tf32(p3));
            }
        #pragma unroll
        for (int r = 0; r < 4; r++) {
            float v = lsum[r];
            v += __shfl_xor_sync(0xffffffffu, v, 1);
            v += __shfl_xor_sync(0xffffffffu, v, 2);
            l_run[r] += v;
        }
        #pragma unroll
        for (int mt = 0; mt < 2; mt++)
            #pragma unroll
            for (int nt = 0; nt < 8; nt++) {
                O[mt][nt][0] *= alpha[2*mt];
                O[mt][nt][1] *= alpha[2*mt];
                O[mt][nt][2] *= alpha[2*mt+1];
                O[mt][nt][3] *= alpha[2*mt+1];
            }
        __syncwarp();

        // ---- PV ----
        #pragma unroll
        for (int kk = 0; kk < 4; kk++) {
            float pa[2][4];
            #pragma unroll
            for (int mt = 0; mt < 2; mt++) {
                int r0 = mt*16 + lg;
                pa[mt][0] = pw[r0*PSTR + kk*8 + lq];
                pa[mt][1] = pw[(r0+8)*PSTR + kk*8 + lq];
                pa[mt][2] = pw[r0*PSTR + kk*8 + lq + 4];
                pa[mt][3] = pw[(r0+8)*PSTR + kk*8 + lq + 4];
            }
            #pragma unroll
            for (int nt = 0; nt < 8; nt++) {
                float bb[2];
                bb[0] = vbuf[(nt*8 + lg)*PSTR + kk*8 + lq];
                bb[1] = vbuf[(nt*8 + lg)*PSTR + kk*8 + lq + 4];
                #pragma unroll
                for (int mt = 0; mt < 2; mt++)
                    mma16n8k8(O[mt][nt], pa[mt], bb);
            }
        }
        __syncthreads();
    }

    // ---- write output ----
    #pragma unroll
    for (int mt = 0; mt < 2; mt++)
        #pragma unroll
        for (int half = 0; half < 2; half++) {
            int row = qt*128 + wid*32 + mt*16 + lg + half*8;
            float inv = 1.f / l_run[2*mt + half];
            float* op = out + ((size_t)(b*SEQ + row)) * (NH*VL) + h*VL;
            #pragma unroll
            for (int nt = 0; nt < 8; nt++)
                *(float2*)&op[nt*8 + 2*lq] = make_float2(O[mt][nt][2*half]*inv,
                                                         O[mt][nt][2*half+1]*inv);
        }
}

// ---------------------------------------------------------------------------
extern "C" void kernel_launch(void* const* d_in, const int* in_sizes, int n_in,
                              void* d_out, int out_size) {
    const float* x   = (const float*)d_in[0];
    const float* Wq  = (const float*)d_in[1];
    const float* bq  = (const float*)d_in[2];
    const float* Wqc = (const float*)d_in[3];
    const float* bqc = (const float*)d_in[4];
    const float* Wk  = (const float*)d_in[5];
    const float* bk  = (const float*)d_in[6];
    const float* Wkc = (const float*)d_in[7];
    const float* bkc = (const float*)d_in[8];
    const float* Wv  = (const float*)d_in[9];
    const float* bv  = (const float*)d_in[10];
    const float* Wvc = (const float*)d_in[11];
    const float* bvc = (const float*)d_in[12];
    float* out = (float*)d_out;

    static bool attr_set = false;
    if (!attr_set) {
        cudaFuncSetAttribute(attn_mma, cudaFuncAttributeMaxDynamicSharedMemorySize, SM_TOT * 4);
        cudaFuncSetAttribute(gemm_mma, cudaFuncAttributeMaxDynamicSharedMemorySize, GSM_TOT * 4);
        attr_set = true;
    }

    fill_bias<<<(NTOT + 255)/256, 256>>>(bq, bqc, bk, bkc, bv, bvc);
    pad_fill<<<(BATCH*16*1280 + 255)/256, 256>>>();
    transpose_w<<<dim3(NTOT/32, DIM/32), 256>>>(Wq, Wqc, Wk, Wkc, Wv, Wvc);
    xcvt<<<(MROWS*DIM/4 + 255)/256, 256>>>(x);

    gemm_mma<<<dim3(NTOT/256, MROWS/128), 256, GSM_TOT * 4>>>();

    attn_mma<<<dim3(SEQ/128, NH, BATCH), 128, SM_TOT * 4>>>(out);
}

// round 14
// speedup vs baseline: 1.7123x; 1.7123x over previous
#include <cuda_runtime.h>
#include <cuda_fp16.h>
#include <cstdint>
#include <math.h>

// Problem constants
#define BATCH 4
#define SEQ   2048
#define SP    2064            // padded sequence (pad = 16)
#define DIM   1024
#define NH    16
#define QL    16
#define VL    64
#define NTOT  3072            // interleaved: col 2p = value, col 2p+1 = gate
#define MROWS (BATCH*SEQ)     // 8192

// -------- device scratch --------
__device__ __half g_Wth[(size_t)NTOT * DIM];    // transposed fp16 weights [n][k]
__device__ __half g_xh[(size_t)MROWS * DIM];    // fp16 x
__device__ float  g_ball[NTOT];
__device__ float  g_q [(size_t)BATCH * NH * SP * QL];   // [bh][s][d] fp32
__device__ __half g_kh[(size_t)BATCH * NH * SP * QL];   // [bh][s][d] fp16 hi
__device__ __half g_kl[(size_t)BATCH * NH * SP * QL];   // [bh][s][d] fp16 lo
__device__ __half g_vh[(size_t)BATCH * NH * VL * SP];   // [bh][d][s] fp16

__device__ __forceinline__ float sigm(float x) { return 1.f / (1.f + __expf(-x)); }

__device__ __forceinline__ uint32_t smem_u32(const void* p) {
    uint32_t a;
    asm("{ .reg .u64 t; cvta.to.shared.u64 t, %1; cvt.u32.u64 %0, t; }" : "=r"(a) : "l"(p));
    return a;
}
__device__ __forceinline__ void cpa16(uint32_t dst, const void* src, bool ok) {
    int sz = ok ? 16 : 0;
    asm volatile("cp.async.cg.shared.global [%0], [%1], 16, %2;"
                 :: "r"(dst), "l"(src), "r"(sz));
}
__device__ __forceinline__ void cpa16u(uint32_t dst, const void* src) {
    asm volatile("cp.async.cg.shared.global [%0], [%1], 16;"
                 :: "r"(dst), "l"(src));
}
#define CPA_COMMIT() asm volatile("cp.async.commit_group;" ::: "memory")

__device__ __forceinline__ void mmaf16(float* d, const uint32_t* a, uint32_t b0, uint32_t b1) {
    asm volatile("mma.sync.aligned.m16n8k16.row.col.f32.f16.f16.f32 "
        "{%0,%1,%2,%3}, {%4,%5,%6,%7}, {%8,%9}, {%0,%1,%2,%3};"
        : "+f"(d[0]), "+f"(d[1]), "+f"(d[2]), "+f"(d[3])
        : "r"(a[0]), "r"(a[1]), "r"(a[2]), "r"(a[3]), "r"(b0), "r"(b1));
}

__device__ __forceinline__ uint32_t packh2(float a, float b) {
    __half2 h = __floats2half2_rn(a, b);
    return *(uint32_t*)&h;
}

// ======================= prep kernels =======================
__global__ void fill_bias(const float* __restrict__ bq,  const float* __restrict__ bqc,
                          const float* __restrict__ bk,  const float* __restrict__ bkc,
                          const float* __restrict__ bv,  const float* __restrict__ bvc) {
    int idx = blockIdx.x * blockDim.x + threadIdx.x;
    if (idx >= NTOT) return;
    int p = idx >> 1;
    bool gate = (idx & 1);
    float bb;
    if (p < 256)      bb = gate ? bqc[p]      : bq[p];
    else if (p < 512) bb = gate ? bkc[p-256]  : bk[p-256];
    else              bb = gate ? bvc[p-512]  : bv[p-512];
    g_ball[idx] = bb;
}

// padded key rows (s in [2048,2064)) bias-only constants for k, v
__global__ void pad_fill() {
    int idx = blockIdx.x * blockDim.x + threadIdx.x;
    const int total = BATCH * 16 * 1280;
    if (idx >= total) return;
    int c = 256 + (idx % 1280);
    int t = idx / 1280;
    int sp = 2048 + (t & 15);
    int b = t >> 4;
    float val = g_ball[2*c] * sigm(g_ball[2*c + 1]);
    if (c < 512) {
        int l = c - 256; int h = l >> 4, d = l & 15;
        size_t off = ((size_t)(b*NH + h) * SP + sp) * QL + d;
        __half hh = __float2half_rn(val);
        g_kh[off] = hh;
        g_kl[off] = __float2half_rn(val - __half2float(hh));
    } else {
        int l = c - 512; int h = l >> 6, d = l & 63;
        g_vh[((size_t)(b*NH + h) * VL + d) * SP + sp] = __float2half_rn(val);
    }
}

__device__ __forceinline__ float fetch_w(int k, int n,
        const float* Wq, const float* Wqc, const float* Wk, const float* Wkc,
        const float* Wv, const float* Wvc) {
    int p = n >> 1;
    bool gate = (n & 1);
    if (p < 256)      return gate ? Wqc[k*256 + p]        : Wq[k*256 + p];
    if (p < 512)      { int l = p-256; return gate ? Wkc[k*256 + l]  : Wk[k*256 + l]; }
    { int l = p-512; return gate ? Wvc[k*1024 + l] : Wv[k*1024 + l]; }
}

// transpose W into g_Wth[n][k] (fp16)
__global__ void transpose_w(const float* __restrict__ Wq,  const float* __restrict__ Wqc,
                            const float* __restrict__ Wk,  const float* __restrict__ Wkc,
                            const float* __restrict__ Wv,  const float* __restrict__ Wvc) {
    __shared__ float tile[32][33];
    int n0 = blockIdx.x * 32, k0 = blockIdx.y * 32;
    int tx = threadIdx.x & 31, ty = threadIdx.x >> 5;
    #pragma unroll
    for (int r = ty; r < 32; r += 8)
        tile[tx][r] = fetch_w(k0 + r, n0 + tx, Wq, Wqc, Wk, Wkc, Wv, Wvc);
    __syncthreads();
    #pragma unroll
    for (int r = ty; r < 32; r += 8)
        g_Wth[(size_t)(n0 + r) * DIM + k0 + tx] = __float2half_rn(tile[r][tx]);
}

// convert x to fp16 (8 elems/thread)
__global__ void xcvt(const float* __restrict__ x) {
    size_t i = ((size_t)blockIdx.x * blockDim.x + threadIdx.x) * 8;
    float4 v0 = *(const float4*)(x + i);
    float4 v1 = *(const float4*)(x + i + 4);
    uint32_t o[4];
    o[0] = packh2(v0.x, v0.y);
    o[1] = packh2(v0.z, v0.w);
    o[2] = packh2(v1.x, v1.y);
    o[3] = packh2(v1.z, v1.w);
    *(uint4*)(((__half*)g_xh) + i) = *(uint4*)o;
}

// ======================= fp16 mma GEMM + CSS epilogue =======================
// C[8192,3072] = x @ W^T, fp16 m16n8k16. CTA 128x128x16, 8 warps (2m x 4n),
// warp tile 64x32. 4-stage cp.async, one __syncthreads per stage.
// smem rows: 16 halves (8 u32) padded to 12 u32 -> conflict-free fragment LDS.
#define GKT 64              // 1024/16 stages
#define GROW 12             // u32 per row
#define GST  1536           // u32 per stage (128 rows * 12)
#define GSMB 6144           // B region offset (u32) = 4*GST
#define GSM_BYTES (12288*4) // 49152

__global__ __launch_bounds__(256, 2) void gemm_mma() {
    extern __shared__ uint32_t smu[];
    const uint32_t smb = smem_u32(smu);

    const int tid  = threadIdx.x;
    const int wid  = tid >> 5, lane = tid & 31;
    const int wm   = wid & 1,  wn   = wid >> 1;
    const int lg   = lane >> 2, lq  = lane & 3;
    const int bm   = blockIdx.y * 128;
    const int bn   = blockIdx.x * 128;

    const int lrow = tid >> 1;       // 0..127
    const int lsel = tid & 1;        // 16B chunk (8 halves)

    // prologue: stages 0..2
    #pragma unroll
    for (int s = 0; s < 3; s++) {
        const int k0 = s * 16;
        cpa16u(smb + (s*GST + lrow*GROW + lsel*4) * 4,
               g_xh + (size_t)(bm + lrow) * DIM + k0 + lsel*8);
        cpa16u(smb + (GSMB + s*GST + lrow*GROW + lsel*4) * 4,
               g_Wth + (size_t)(bn + lrow) * DIM + k0 + lsel*8);
        CPA_COMMIT();
    }

    float acc[4][4][4];
    #pragma unroll
    for (int i = 0; i < 4; i++)
        #pragma unroll
        for (int j = 0; j < 4; j++)
            #pragma unroll
            for (int r = 0; r < 4; r++) acc[i][j][r] = 0.f;

    for (int t = 0; t < GKT; t++) {
        asm volatile("cp.async.wait_group 2;" ::: "memory");
        __syncthreads();
        if (t + 3 < GKT) {
            const int k0 = (t + 3) * 16;
            const int ab = (t + 3) & 3;
            cpa16u(smb + (ab*GST + lrow*GROW + lsel*4) * 4,
                   g_xh + (size_t)(bm + lrow) * DIM + k0 + lsel*8);
            cpa16u(smb + (GSMB + ab*GST + lrow*GROW + lsel*4) * 4,
                   g_Wth + (size_t)(bn + lrow) * DIM + k0 + lsel*8);
        }
        CPA_COMMIT();

        const uint32_t* Ab = smu + (t & 3) * GST;
        const uint32_t* Bb = smu + GSMB + (t & 3) * GST;

        uint32_t a[4][4], b[4][2];
        #pragma unroll
        for (int mt = 0; mt < 4; mt++) {
            int r0 = wm*64 + mt*16 + lg;
            a[mt][0] = Ab[r0*GROW + lq];
            a[mt][1] = Ab[(r0+8)*GROW + lq];
            a[mt][2] = Ab[r0*GROW + lq + 4];
            a[mt][3] = Ab[(r0+8)*GROW + lq + 4];
        }
        #pragma unroll
        for (int nt = 0; nt < 4; nt++) {
            int n0 = wn*32 + nt*8 + lg;
            b[nt][0] = Bb[n0*GROW + lq];
            b[nt][1] = Bb[n0*GROW + lq + 4];
        }
        #pragma unroll
        for (int mt = 0; mt < 4; mt++)
            #pragma unroll
            for (int nt = 0; nt < 4; nt++)
                mmaf16(acc[mt][nt], a[mt], b[nt][0], b[nt][1]);
    }

    // ---- epilogue: CSS gate + scatter (c0,c1)=(value,gate) per thread ----
    #pragma unroll
    for (int mt = 0; mt < 4; mt++) {
        int mrow0 = bm + wm*64 + mt*16 + lg;
        #pragma unroll
        for (int nt = 0; nt < 4; nt++) {
            int jc = bn + wn*32 + nt*8 + 2*lq;   // packed col of c0 (even)
            float bv = g_ball[jc];
            float bg = g_ball[jc + 1];
            int p = jc >> 1;
            #pragma unroll
            for (int half_ = 0; half_ < 2; half_++) {
                int m = mrow0 + 8*half_;
                float val = (acc[mt][nt][2*half_] + bv) * sigm(acc[mt][nt][2*half_ + 1] + bg);
                int b_ = m >> 11;
                int s  = m & 2047;
                if (p < 256) {
                    g_q[((size_t)(b_*NH + (p >> 4)) * SP + s) * QL + (p & 15)] = val;
                } else if (p < 512) {
                    int l = p - 256;
                    size_t off = ((size_t)(b_*NH + (l >> 4)) * SP + s) * QL + (l & 15);
                    __half hh = __float2half_rn(val);
                    g_kh[off] = hh;
                    g_kl[off] = __float2half_rn(val - __half2float(hh));
                } else {
                    int l = p - 512;
                    g_vh[((size_t)(b_*NH + (l >> 6)) * VL + (l & 63)) * SP + s] = __float2half_rn(val);
                }
            }
        }
    }
}

// ======================= fp16 tensor-core flash attention =======================
// CTA: 128 q-rows, 4 warps. 32-key tiles, 3-stage cp.async pipeline.
// QK: fp16 hi/lo x3 (one k16 covers QL=16). PV: fp16 P (half2) x fp16 V.
// smem (4B units):
#define SA_Q   0         // q fp32 staging: 128*20 = 2560
#define SA_KH  2560      // 3 stages * 384 (32 rows * 12 u32)
#define SA_KL  3712      // 3 * 384
#define SA_VH  4864      // 3 stages * 1280 (64 rows * 20 u32)
#define SA_P   8704      // 4 warps * 640 (32 rows * 20 u32)
#define SA_TOT 11264     // 45056 bytes

__global__ __launch_bounds__(128) void attn_mma(float* __restrict__ out) {
    extern __shared__ uint32_t smu[];
    float* smf = (float*)smu;
    const int qt = blockIdx.x, h = blockIdx.y, b = blockIdx.z;
    const int bh = b * NH + h;

    const int tid = threadIdx.x;
    const int wid = tid >> 5, lane = tid & 31;
    const int lg = lane >> 2, lq = lane & 3;

    const __half* khb = g_kh + (size_t)bh * SP * QL;
    const __half* klb = g_kl + (size_t)bh * SP * QL;
    const __half* vhb = g_vh + (size_t)bh * VL * SP;

    const uint32_t smb = smem_u32(smu);
    const int NKT = (SP + 31) / 32;   // 65

    // K loader: row = tid>>2 (0..31), sel = tid&3 (hi/lo x 2 chunks)
    const int krow = tid >> 2, ksel = tid & 3;
    const bool khi_ = (ksel < 2);
    const int kchunk = ksel & 1;

    // ---- stage Q tile [128][16] fp32 ----
    {
        const float* src = g_q + ((size_t)bh * SP + qt*128 + tid) * QL;
        #pragma unroll
        for (int u = 0; u < 4; u++)
            *(float4*)&smf[SA_Q + tid*20 + u*4] = *(const float4*)(src + u*4);
    }

    // prologue: issue tiles 0,1
    #pragma unroll
    for (int pt = 0; pt < 2; pt++) {
        const int k0 = pt * 32;
        {
            int gk = k0 + krow;
            bool ok = gk < SP;
            uint32_t dst = smb + ((khi_ ? SA_KH : SA_KL) + pt*384 + krow*12 + kchunk*4) * 4;
            const __half* src = (khi_ ? khb : klb) + (size_t)(ok ? gk : 0) * QL + kchunk*8;
            cpa16(dst, src, ok);
        }
        #pragma unroll
        for (int it = 0; it < 2; it++) {
            int chunk = it * 128 + tid;
            int d = chunk >> 2, c = chunk & 3;
            bool ok = (k0 + c*8 + 8) <= SP;
            uint32_t dst = smb + (SA_VH + pt*1280 + d*20 + c*4) * 4;
            cpa16(dst, vhb + (size_t)d * SP + (ok ? k0 + c*8 : 0), ok);
        }
        CPA_COMMIT();
    }
    __syncthreads();

    // Q fragments fp16 hi/lo (scale 0.125 folded)
    uint32_t qh[2][4], ql[2][4];
    #pragma unroll
    for (int mt = 0; mt < 2; mt++) {
        int r0 = wid*32 + mt*16 + lg;
        #pragma unroll
        for (int e = 0; e < 4; e++) {
            int rr = r0 + ((e & 1) ? 8 : 0);
            int cc = 2*lq + ((e >= 2) ? 8 : 0);
            float f0 = smf[SA_Q + rr*20 + cc]     * 0.125f;
            float f1 = smf[SA_Q + rr*20 + cc + 1] * 0.125f;
            __half h0 = __float2half_rn(f0), h1 = __float2half_rn(f1);
            qh[mt][e] = packh2(f0, f1);
            ql[mt][e] = packh2(f0 - __half2float(h0), f1 - __half2float(h1));
        }
    }

    float O[2][8][4];
    #pragma unroll
    for (int mt = 0; mt < 2; mt++)
        #pragma unroll
        for (int nt = 0; nt < 8; nt++)
            #pragma unroll
            for (int c = 0; c < 4; c++) O[mt][nt][c] = 0.f;
    float m_run[4], l_run[4];
    #pragma unroll
    for (int r = 0; r < 4; r++) { m_run[r] = -1e30f; l_run[r] = 0.f; }

    uint32_t* pwu = smu + SA_P + wid * 640;

    for (int kt = 0; kt < NKT; kt++) {
        const int k0 = kt * 32;
        if (kt + 1 < NKT) asm volatile("cp.async.wait_group 1;" ::: "memory");
        else              asm volatile("cp.async.wait_group 0;" ::: "memory");
        __syncthreads();
        if (kt + 2 < NKT) {
            const int k2 = (kt + 2) * 32;
            const int bi = (kt + 2) % 3;
            {
                int gk = k2 + krow;
                bool ok = gk < SP;
                uint32_t dst = smb + ((khi_ ? SA_KH : SA_KL) + bi*384 + krow*12 + kchunk*4) * 4;
                const __half* src = (khi_ ? khb : klb) + (size_t)(ok ? gk : 0) * QL + kchunk*8;
                cpa16(dst, src, ok);
            }
            #pragma unroll
            for (int it = 0; it < 2; it++) {
                int chunk = it * 128 + tid;
                int d = chunk >> 2, c = chunk & 3;
                bool ok = (k2 + c*8 + 8) <= SP;
                uint32_t dst = smb + (SA_VH + bi*1280 + d*20 + c*4) * 4;
                cpa16(dst, vhb + (size_t)d * SP + (ok ? k2 + c*8 : 0), ok);
            }
            CPA_COMMIT();
        }

        const uint32_t* KH = smu + SA_KH + (kt % 3) * 384;
        const uint32_t* KL = smu + SA_KL + (kt % 3) * 384;
        const uint32_t* VH = smu + SA_VH + (kt % 3) * 1280;

        // ---- QK (fp16 hi/lo, 3 mma per tile-pair) ----
        float sc[2][4][4];
        #pragma unroll
        for (int mt = 0; mt < 2; mt++)
            #pragma unroll
            for (int nt = 0; nt < 4; nt++)
                #pragma unroll
                for (int c = 0; c < 4; c++) sc[mt][nt][c] = 0.f;
        #pragma unroll
        for (int nt = 0; nt < 4; nt++) {
            int n0 = nt*8 + lg;
            uint32_t bh0 = KH[n0*12 + lq], bh1 = KH[n0*12 + lq + 4];
            uint32_t bl0 = KL[n0*12 + lq], bl1 = KL[n0*12 + lq + 4];
            #pragma unroll
            for (int mt = 0; mt < 2; mt++) {
                mmaf16(sc[mt][nt], qh[mt], bh0, bh1);
                mmaf16(sc[mt][nt], ql[mt], bh0, bh1);
                mmaf16(sc[mt][nt], qh[mt], bl0, bl1);
            }
        }
        if (k0 + 32 > SP) {
            #pragma unroll
            for (int nt = 0; nt < 4; nt++)
                #pragma unroll
                for (int c = 0; c < 4; c++) {
                    int col = k0 + nt*8 + 2*lq + (c & 1);
                    if (col >= SP) { sc[0][nt][c] = -1e30f; sc[1][nt][c] = -1e30f; }
                }
        }

        // ---- softmax ----
        float mloc[4];
        #pragma unroll
        for (int mt = 0; mt < 2; mt++) {
            float v0 = fmaxf(fmaxf(sc[mt][0][0], sc[mt][0][1]), fmaxf(sc[mt][1][0], sc[mt][1][1]));
            v0 = fmaxf(v0, fmaxf(fmaxf(sc[mt][2][0], sc[mt][2][1]), fmaxf(sc[mt][3][0], sc[mt][3][1])));
            float v1 = fmaxf(fmaxf(sc[mt][0][2], sc[mt][0][3]), fmaxf(sc[mt][1][2], sc[mt][1][3]));
            v1 = fmaxf(v1, fmaxf(fmaxf(sc[mt][2][2], sc[mt][2][3]), fmaxf(sc[mt][3][2], sc[mt][3][3])));
            mloc[2*mt]   = v0;
            mloc[2*mt+1] = v1;
        }
        #pragma unroll
        for (int r = 0; r < 4; r++) {
            float v = mloc[r];
            v = fmaxf(v, __shfl_xor_sync(0xffffffffu, v, 1));
            v = fmaxf(v, __shfl_xor_sync(0xffffffffu, v, 2));
            mloc[r] = v;
        }
        float alpha[4];
        #pragma unroll
        for (int r = 0; r < 4; r++) {
            float mn = fmaxf(m_run[r], mloc[r]);
            alpha[r] = __expf(m_run[r] - mn);
            m_run[r] = mn;
            l_run[r] *= alpha[r];
        }
        float lsum[4] = {0.f, 0.f, 0.f, 0.f};
        #pragma unroll
        for (int mt = 0; mt < 2; mt++)
            #pragma unroll
            for (int nt = 0; nt < 4; nt++) {
                float p0 = __expf(sc[mt][nt][0] - m_run[2*mt]);
                float p1 = __expf(sc[mt][nt][1] - m_run[2*mt]);
                float p2 = __expf(sc[mt][nt][2] - m_run[2*mt+1]);
                float p3 = __expf(sc[mt][nt][3] - m_run[2*mt+1]);
                lsum[2*mt]   += p0 + p1;
                lsum[2*mt+1] += p2 + p3;
                pwu[(mt*16 + lg)*20     + nt*4 + lq] = packh2(p0, p1);
                pwu[(mt*16 + lg + 8)*20 + nt*4 + lq] = packh2(p2, p3);
            }
        #pragma unroll
        for (int r = 0; r < 4; r++) {
            float v = lsum[r];
            v += __shfl_xor_sync(0xffffffffu, v, 1);
            v += __shfl_xor_sync(0xffffffffu, v, 2);
            l_run[r] += v;
        }
        #pragma unroll
        for (int mt = 0; mt < 2; mt++)
            #pragma unroll
            for (int nt = 0; nt < 8; nt++) {
                O[mt][nt][0] *= alpha[2*mt];
                O[mt][nt][1] *= alpha[2*mt];
                O[mt][nt][2] *= alpha[2*mt+1];
                O[mt][nt][3] *= alpha[2*mt+1];
            }
        __syncwarp();

        // ---- PV (fp16, 2 k16 chunks over 32 keys) ----
        #pragma unroll
        for (int kk = 0; kk < 2; kk++) {
            uint32_t pa[2][4];
            #pragma unroll
            for (int mt = 0; mt < 2; mt++) {
                int r0 = mt*16 + lg;
                pa[mt][0] = pwu[r0*20 + kk*8 + lq];
                pa[mt][1] = pwu[(r0+8)*20 + kk*8 + lq];
                pa[mt][2] = pwu[r0*20 + kk*8 + lq + 4];
                pa[mt][3] = pwu[(r0+8)*20 + kk*8 + lq + 4];
            }
            #pragma unroll
            for (int nt = 0; nt < 8; nt++) {
                int n0 = nt*8 + lg;
                uint32_t b0 = VH[n0*20 + kk*8 + lq];
                uint32_t b1 = VH[n0*20 + kk*8 + lq + 4];
                #pragma unroll
                for (int mt = 0; mt < 2; mt++)
                    mmaf16(O[mt][nt], pa[mt], b0, b1);
            }
        }
        __syncthreads();   // protect buffer (kt%3) before re-issue
    }

    // ---- write output ----
    #pragma unroll
    for (int mt = 0; mt < 2; mt++)
        #pragma unroll
        for (int half_ = 0; half_ < 2; half_++) {
            int row = qt*128 + wid*32 + mt*16 + lg + half_*8;
            float inv = 1.f / l_run[2*mt + half_];
            float* op = out + ((size_t)(b*SEQ + row)) * (NH*VL) + h*VL;
            #pragma unroll
            for (int nt = 0; nt < 8; nt++)
                *(float2*)&op[nt*8 + 2*lq] = make_float2(O[mt][nt][2*half_]*inv,
                                                         O[mt][nt][2*half_+1]*inv);
        }
}

// ---------------------------------------------------------------------------
extern "C" void kernel_launch(void* const* d_in, const int* in_sizes, int n_in,
                              void* d_out, int out_size) {
    const float* x   = (const float*)d_in[0];
    const float* Wq  = (const float*)d_in[1];
    const float* bq  = (const float*)d_in[2];
    const float* Wqc = (const float*)d_in[3];
    const float* bqc = (const float*)d_in[4];
    const float* Wk  = (const float*)d_in[5];
    const float* bk  = (const float*)d_in[6];
    const float* Wkc = (const float*)d_in[7];
    const float* bkc = (const float*)d_in[8];
    const float* Wv  = (const float*)d_in[9];
    const float* bv  = (const float*)d_in[10];
    const float* Wvc = (const float*)d_in[11];
    const float* bvc = (const float*)d_in[12];
    float* out = (float*)d_out;

    static bool attr_set = false;
    if (!attr_set) {
        cudaFuncSetAttribute(attn_mma, cudaFuncAttributeMaxDynamicSharedMemorySize, SA_TOT * 4);
        cudaFuncSetAttribute(gemm_mma, cudaFuncAttributeMaxDynamicSharedMemorySize, GSM_BYTES);
        attr_set = true;
    }

    fill_bias<<<(NTOT + 255)/256, 256>>>(bq, bqc, bk, bkc, bv, bvc);
    pad_fill<<<(BATCH*16*1280 + 255)/256, 256>>>();
    transpose_w<<<dim3(NTOT/32, DIM/32), 256>>>(Wq, Wqc, Wk, Wkc, Wv, Wvc);
    xcvt<<<(MROWS*DIM/8 + 255)/256, 256>>>(x);

    gemm_mma<<<dim3(NTOT/128, MROWS/128), 256, GSM_BYTES>>>();

    attn_mma<<<dim3(SEQ/128, NH, BATCH), 128, SA_TOT * 4>>>(out);
}

// round 15
// speedup vs baseline: 1.7682x; 1.0327x over previous
#include <cuda_runtime.h>
#include <cuda_fp16.h>
#include <cstdint>
#include <math.h>

// Problem constants
#define BATCH 4
#define SEQ   2048
#define SP    2064            // padded sequence (pad = 16)
#define DIM   1024
#define NH    16
#define QL    16
#define VL    64
#define NTOT  3072            // interleaved: col 2p = value, col 2p+1 = gate
#define MROWS (BATCH*SEQ)     // 8192

// -------- device scratch --------
__device__ __half g_Wth[(size_t)NTOT * DIM];    // transposed fp16 weights [n][k]
__device__ __half g_xh[(size_t)MROWS * DIM];    // fp16 x
__device__ float  g_ball[NTOT];
__device__ float  g_q [(size_t)BATCH * NH * SP * QL];   // [bh][s][d] fp32
__device__ __half g_kh[(size_t)BATCH * NH * SP * QL];   // [bh][s][d] fp16 hi
__device__ __half g_kl[(size_t)BATCH * NH * SP * QL];   // [bh][s][d] fp16 lo
__device__ __half g_vh[(size_t)BATCH * NH * VL * SP];   // [bh][d][s] fp16

__device__ __forceinline__ float sigm(float x) { return 1.f / (1.f + __expf(-x)); }

__device__ __forceinline__ uint32_t smem_u32(const void* p) {
    uint32_t a;
    asm("{ .reg .u64 t; cvta.to.shared.u64 t, %1; cvt.u32.u64 %0, t; }" : "=r"(a) : "l"(p));
    return a;
}
__device__ __forceinline__ void cpa16(uint32_t dst, const void* src, bool ok) {
    int sz = ok ? 16 : 0;
    asm volatile("cp.async.cg.shared.global [%0], [%1], 16, %2;"
                 :: "r"(dst), "l"(src), "r"(sz));
}
__device__ __forceinline__ void cpa16u(uint32_t dst, const void* src) {
    asm volatile("cp.async.cg.shared.global [%0], [%1], 16;"
                 :: "r"(dst), "l"(src));
}
#define CPA_COMMIT() asm volatile("cp.async.commit_group;" ::: "memory")

__device__ __forceinline__ void mmaf16(float* d, const uint32_t* a, uint32_t b0, uint32_t b1) {
    asm volatile("mma.sync.aligned.m16n8k16.row.col.f32.f16.f16.f32 "
        "{%0,%1,%2,%3}, {%4,%5,%6,%7}, {%8,%9}, {%0,%1,%2,%3};"
        : "+f"(d[0]), "+f"(d[1]), "+f"(d[2]), "+f"(d[3])
        : "r"(a[0]), "r"(a[1]), "r"(a[2]), "r"(a[3]), "r"(b0), "r"(b1));
}

__device__ __forceinline__ uint32_t packh2(float a, float b) {
    __half2 h = __floats2half2_rn(a, b);
    return *(uint32_t*)&h;
}

// ======================= fused prep kernel =======================
__device__ __forceinline__ float fetch_w(int k, int n,
        const float* Wq, const float* Wqc, const float* Wk, const float* Wkc,
        const float* Wv, const float* Wvc) {
    int p = n >> 1;
    bool gate = (n & 1);
    if (p < 256)      return gate ? Wqc[k*256 + p]        : Wq[k*256 + p];
    if (p < 512)      { int l = p-256; return gate ? Wkc[k*256 + l]  : Wk[k*256 + l]; }
    { int l = p-512; return gate ? Wvc[k*1024 + l] : Wv[k*1024 + l]; }
}

// grid sections: [0,3072) transpose_w, [3072,7168) xcvt, [7168,7180) fill_bias,
// [7180,7500) pad_fill. 256 threads.
__global__ void prep(const float* __restrict__ x,
                     const float* __restrict__ Wq,  const float* __restrict__ bq,
                     const float* __restrict__ Wqc, const float* __restrict__ bqc,
                     const float* __restrict__ Wk,  const float* __restrict__ bk,
                     const float* __restrict__ Wkc, const float* __restrict__ bkc,
                     const float* __restrict__ Wv,  const float* __restrict__ bv,
                     const float* __restrict__ Wvc, const float* __restrict__ bvc) {
    const int blk = blockIdx.x;
    if (blk < 3072) {
        // transpose W -> g_Wth[n][k] fp16
        __shared__ float tile[32][33];
        int n0 = (blk % 96) * 32, k0 = (blk / 96) * 32;
        int tx = threadIdx.x & 31, ty = threadIdx.x >> 5;
        #pragma unroll
        for (int r = ty; r < 32; r += 8)
            tile[tx][r] = fetch_w(k0 + r, n0 + tx, Wq, Wqc, Wk, Wkc, Wv, Wvc);
        __syncthreads();
        #pragma unroll
        for (int r = ty; r < 32; r += 8)
            g_Wth[(size_t)(n0 + r) * DIM + k0 + tx] = __float2half_rn(tile[r][tx]);
    } else if (blk < 7168) {
        // x -> fp16 (8 elems/thread)
        size_t i = ((size_t)(blk - 3072) * 256 + threadIdx.x) * 8;
        float4 v0 = *(const float4*)(x + i);
        float4 v1 = *(const float4*)(x + i + 4);
        uint32_t o[4];
        o[0] = packh2(v0.x, v0.y);
        o[1] = packh2(v0.z, v0.w);
        o[2] = packh2(v1.x, v1.y);
        o[3] = packh2(v1.z, v1.w);
        *(uint4*)(((__half*)g_xh) + i) = *(uint4*)o;
    } else if (blk < 7180) {
        // fill interleaved bias
        int idx = (blk - 7168) * 256 + threadIdx.x;
        if (idx < NTOT) {
            int p = idx >> 1;
            bool gate = (idx & 1);
            float bb;
            if (p < 256)      bb = gate ? bqc[p]      : bq[p];
            else if (p < 512) bb = gate ? bkc[p-256]  : bk[p-256];
            else              bb = gate ? bvc[p-512]  : bv[p-512];
            g_ball[idx] = bb;
        }
    } else {
        // pad rows (s in [2048,2064)) for k hi/lo + v; bias computed inline
        int idx = (blk - 7180) * 256 + threadIdx.x;
        const int total = BATCH * 16 * 1280;
        if (idx >= total) return;
        int c = 256 + (idx % 1280);        // value-col in [256,1536)
        int t = idx / 1280;
        int sp = 2048 + (t & 15);
        int b = t >> 4;
        float bval, bgate;
        if (c < 512) { bval = bk[c-256]; bgate = bkc[c-256]; }
        else         { bval = bv[c-512]; bgate = bvc[c-512]; }
        float val = bval * sigm(bgate);
        if (c < 512) {
            int l = c - 256; int h = l >> 4, d = l & 15;
            size_t off = ((size_t)(b*NH + h) * SP + sp) * QL + d;
            __half hh = __float2half_rn(val);
            g_kh[off] = hh;
            g_kl[off] = __float2half_rn(val - __half2float(hh));
        } else {
            int l = c - 512; int h = l >> 6, d = l & 63;
            g_vh[((size_t)(b*NH + h) * VL + d) * SP + sp] = __float2half_rn(val);
        }
    }
}

// ======================= fp16 mma GEMM + CSS epilogue =======================
// C[8192,3072] = x @ W^T, fp16 m16n8k16. CTA 128x128x16, 8 warps (2m x 4n),
// warp tile 64x32. 4-stage cp.async, one __syncthreads per stage.
#define GKT 64              // 1024/16 stages
#define GROW 12             // u32 per row
#define GST  1536           // u32 per stage (128 rows * 12)
#define GSMB 6144           // B region offset (u32) = 4*GST
#define GSM_BYTES (12288*4) // 49152

__global__ __launch_bounds__(256, 2) void gemm_mma() {
    extern __shared__ uint32_t smu[];
    const uint32_t smb = smem_u32(smu);

    const int tid  = threadIdx.x;
    const int wid  = tid >> 5, lane = tid & 31;
    const int wm   = wid & 1,  wn   = wid >> 1;
    const int lg   = lane >> 2, lq  = lane & 3;
    const int bm   = blockIdx.y * 128;
    const int bn   = blockIdx.x * 128;

    const int lrow = tid >> 1;       // 0..127
    const int lsel = tid & 1;        // 16B chunk (8 halves)

    // prologue: stages 0..2
    #pragma unroll
    for (int s = 0; s < 3; s++) {
        const int k0 = s * 16;
        cpa16u(smb + (s*GST + lrow*GROW + lsel*4) * 4,
               g_xh + (size_t)(bm + lrow) * DIM + k0 + lsel*8);
        cpa16u(smb + (GSMB + s*GST + lrow*GROW + lsel*4) * 4,
               g_Wth + (size_t)(bn + lrow) * DIM + k0 + lsel*8);
        CPA_COMMIT();
    }

    float acc[4][4][4];
    #pragma unroll
    for (int i = 0; i < 4; i++)
        #pragma unroll
        for (int j = 0; j < 4; j++)
            #pragma unroll
            for (int r = 0; r < 4; r++) acc[i][j][r] = 0.f;

    for (int t = 0; t < GKT; t++) {
        asm volatile("cp.async.wait_group 2;" ::: "memory");
        __syncthreads();
        if (t + 3 < GKT) {
            const int k0 = (t + 3) * 16;
            const int ab = (t + 3) & 3;
            cpa16u(smb + (ab*GST + lrow*GROW + lsel*4) * 4,
                   g_xh + (size_t)(bm + lrow) * DIM + k0 + lsel*8);
            cpa16u(smb + (GSMB + ab*GST + lrow*GROW + lsel*4) * 4,
                   g_Wth + (size_t)(bn + lrow) * DIM + k0 + lsel*8);
        }
        CPA_COMMIT();

        const uint32_t* Ab = smu + (t & 3) * GST;
        const uint32_t* Bb = smu + GSMB + (t & 3) * GST;

        uint32_t a[4][4], b[4][2];
        #pragma unroll
        for (int mt = 0; mt < 4; mt++) {
            int r0 = wm*64 + mt*16 + lg;
            a[mt][0] = Ab[r0*GROW + lq];
            a[mt][1] = Ab[(r0+8)*GROW + lq];
            a[mt][2] = Ab[r0*GROW + lq + 4];
            a[mt][3] = Ab[(r0+8)*GROW + lq + 4];
        }
        #pragma unroll
        for (int nt = 0; nt < 4; nt++) {
            int n0 = wn*32 + nt*8 + lg;
            b[nt][0] = Bb[n0*GROW + lq];
            b[nt][1] = Bb[n0*GROW + lq + 4];
        }
        #pragma unroll
        for (int mt = 0; mt < 4; mt++)
            #pragma unroll
            for (int nt = 0; nt < 4; nt++)
                mmaf16(acc[mt][nt], a[mt], b[nt][0], b[nt][1]);
    }

    // ---- epilogue: CSS gate + scatter (c0,c1)=(value,gate) per thread ----
    #pragma unroll
    for (int mt = 0; mt < 4; mt++) {
        int mrow0 = bm + wm*64 + mt*16 + lg;
        #pragma unroll
        for (int nt = 0; nt < 4; nt++) {
            int jc = bn + wn*32 + nt*8 + 2*lq;   // packed col of c0 (even)
            float bv = g_ball[jc];
            float bg = g_ball[jc + 1];
            int p = jc >> 1;
            #pragma unroll
            for (int half_ = 0; half_ < 2; half_++) {
                int m = mrow0 + 8*half_;
                float val = (acc[mt][nt][2*half_] + bv) * sigm(acc[mt][nt][2*half_ + 1] + bg);
                int b_ = m >> 11;
                int s  = m & 2047;
                if (p < 256) {
                    g_q[((size_t)(b_*NH + (p >> 4)) * SP + s) * QL + (p & 15)] = val;
                } else if (p < 512) {
                    int l = p - 256;
                    size_t off = ((size_t)(b_*NH + (l >> 4)) * SP + s) * QL + (l & 15);
                    __half hh = __float2half_rn(val);
                    g_kh[off] = hh;
                    g_kl[off] = __float2half_rn(val - __half2float(hh));
                } else {
                    int l = p - 512;
                    g_vh[((size_t)(b_*NH + (l >> 6)) * VL + (l & 63)) * SP + s] = __float2half_rn(val);
                }
            }
        }
    }
}

// ======================= fp16 tensor-core flash attention =======================
// CTA: 128 q-rows, 4 warps. 64-key tiles, 3-stage cp.async pipeline.
// QK: fp16 hi/lo x3. PV: fp16. One __syncthreads per tile.
// smem layout (u32):
#define SA_Q   0         // q fp32 staging: 128*20 = 2560
#define SA_KH  2560      // 3 stages * 768 (64 rows * 12 u32)
#define SA_KL  4864      // 3 * 768
#define SA_VH  7168      // 3 stages * 2304 (64 d-rows * 36 u32)
#define SA_P   14080     // 4 warps * 1152 (32 rows * 36 u32)
#define SA_TOT 18688     // 74752 bytes

__global__ __launch_bounds__(128) void attn_mma(float* __restrict__ out) {
    extern __shared__ uint32_t smu[];
    float* smf = (float*)smu;
    const int qt = blockIdx.x, h = blockIdx.y, b = blockIdx.z;
    const int bh = b * NH + h;

    const int tid = threadIdx.x;
    const int wid = tid >> 5, lane = tid & 31;
    const int lg = lane >> 2, lq = lane & 3;

    const __half* khb = g_kh + (size_t)bh * SP * QL;
    const __half* klb = g_kl + (size_t)bh * SP * QL;
    const __half* vhb = g_vh + (size_t)bh * VL * SP;

    const uint32_t smb = smem_u32(smu);
    const int NKT = (SP + 63) / 64;   // 33

    // K loader: row = tid>>1 (0..63), chunk = tid&1 (two 16B per row); hi AND lo
    const int krow = tid >> 1, kchunk = tid & 1;

    // ---- stage Q tile [128][16] fp32 ----
    {
        const float* src = g_q + ((size_t)bh * SP + qt*128 + tid) * QL;
        #pragma unroll
        for (int u = 0; u < 4; u++)
            *(float4*)&smf[SA_Q + tid*20 + u*4] = *(const float4*)(src + u*4);
    }

    // prologue: issue tiles 0,1
    #pragma unroll
    for (int pt = 0; pt < 2; pt++) {
        const int k0 = pt * 64;
        {
            int gk = k0 + krow;
            bool ok = gk < SP;
            cpa16(smb + (SA_KH + pt*768 + krow*12 + kchunk*4) * 4,
                  khb + (size_t)(ok ? gk : 0) * QL + kchunk*8, ok);
            cpa16(smb + (SA_KL + pt*768 + krow*12 + kchunk*4) * 4,
                  klb + (size_t)(ok ? gk : 0) * QL + kchunk*8, ok);
        }
        #pragma unroll
        for (int it = 0; it < 4; it++) {
            int chunk = it * 128 + tid;
            int d = chunk >> 3, kc = chunk & 7;
            bool ok = (k0 + kc*8 + 8) <= SP;
            cpa16(smb + (SA_VH + pt*2304 + d*36 + kc*4) * 4,
                  vhb + (size_t)d * SP + (ok ? k0 + kc*8 : 0), ok);
        }
        CPA_COMMIT();
    }
    __syncthreads();

    // Q fragments fp16 hi/lo (scale 0.125 folded)
    uint32_t qh[2][4], ql[2][4];
    #pragma unroll
    for (int mt = 0; mt < 2; mt++) {
        int r0 = wid*32 + mt*16 + lg;
        #pragma unroll
        for (int e = 0; e < 4; e++) {
            int rr = r0 + ((e & 1) ? 8 : 0);
            int cc = 2*lq + ((e >= 2) ? 8 : 0);
            float f0 = smf[SA_Q + rr*20 + cc]     * 0.125f;
            float f1 = smf[SA_Q + rr*20 + cc + 1] * 0.125f;
            __half h0 = __float2half_rn(f0), h1 = __float2half_rn(f1);
            qh[mt][e] = packh2(f0, f1);
            ql[mt][e] = packh2(f0 - __half2float(h0), f1 - __half2float(h1));
        }
    }

    float O[2][8][4];
    #pragma unroll
    for (int mt = 0; mt < 2; mt++)
        #pragma unroll
        for (int nt = 0; nt < 8; nt++)
            #pragma unroll
            for (int c = 0; c < 4; c++) O[mt][nt][c] = 0.f;
    float m_run[4], l_run[4];
    #pragma unroll
    for (int r = 0; r < 4; r++) { m_run[r] = -1e30f; l_run[r] = 0.f; }

    uint32_t* pwu = smu + SA_P + wid * 1152;

    for (int kt = 0; kt < NKT; kt++) {
        const int k0 = kt * 64;
        if (kt + 1 < NKT) asm volatile("cp.async.wait_group 1;" ::: "memory");
        else              asm volatile("cp.async.wait_group 0;" ::: "memory");
        __syncthreads();
        if (kt + 2 < NKT) {
            const int k2 = (kt + 2) * 64;
            const int bi = (kt + 2) % 3;
            {
                int gk = k2 + krow;
                bool ok = gk < SP;
                cpa16(smb + (SA_KH + bi*768 + krow*12 + kchunk*4) * 4,
                      khb + (size_t)(ok ? gk : 0) * QL + kchunk*8, ok);
                cpa16(smb + (SA_KL + bi*768 + krow*12 + kchunk*4) * 4,
                      klb + (size_t)(ok ? gk : 0) * QL + kchunk*8, ok);
            }
            #pragma unroll
            for (int it = 0; it < 4; it++) {
                int chunk = it * 128 + tid;
                int d = chunk >> 3, kc = chunk & 7;
                bool ok = (k2 + kc*8 + 8) <= SP;
                cpa16(smb + (SA_VH + bi*2304 + d*36 + kc*4) * 4,
                      vhb + (size_t)d * SP + (ok ? k2 + kc*8 : 0), ok);
            }
            CPA_COMMIT();
        }

        const uint32_t* KH = smu + SA_KH + (kt % 3) * 768;
        const uint32_t* KL = smu + SA_KL + (kt % 3) * 768;
        const uint32_t* VH = smu + SA_VH + (kt % 3) * 2304;

        // ---- QK (fp16 hi/lo, 3 mma per n-tile) ----
        float sc[2][8][4];
        #pragma unroll
        for (int mt = 0; mt < 2; mt++)
            #pragma unroll
            for (int nt = 0; nt < 8; nt++)
                #pragma unroll
                for (int c = 0; c < 4; c++) sc[mt][nt][c] = 0.f;
        #pragma unroll
        for (int nt = 0; nt < 8; nt++) {
            int n0 = nt*8 + lg;
            uint32_t bh0 = KH[n0*12 + lq], bh1 = KH[n0*12 + lq + 4];
            uint32_t bl0 = KL[n0*12 + lq], bl1 = KL[n0*12 + lq + 4];
            #pragma unroll
            for (int mt = 0; mt < 2; mt++) {
                mmaf16(sc[mt][nt], qh[mt], bh0, bh1);
                mmaf16(sc[mt][nt], ql[mt], bh0, bh1);
                mmaf16(sc[mt][nt], qh[mt], bl0, bl1);
            }
        }
        if (k0 + 64 > SP) {
            #pragma unroll
            for (int nt = 0; nt < 8; nt++)
                #pragma unroll
                for (int c = 0; c < 4; c++) {
                    int col = k0 + nt*8 + 2*lq + (c & 1);
                    if (col >= SP) { sc[0][nt][c] = -1e30f; sc[1][nt][c] = -1e30f; }
                }
        }

        // ---- softmax ----
        float mloc[4];
        #pragma unroll
        for (int mt = 0; mt < 2; mt++) {
            float v0 = -1e30f, v1 = -1e30f;
            #pragma unroll
            for (int nt = 0; nt < 8; nt++) {
                v0 = fmaxf(v0, fmaxf(sc[mt][nt][0], sc[mt][nt][1]));
                v1 = fmaxf(v1, fmaxf(sc[mt][nt][2], sc[mt][nt][3]));
            }
            mloc[2*mt]   = v0;
            mloc[2*mt+1] = v1;
        }
        #pragma unroll
        for (int r = 0; r < 4; r++) {
            float v = mloc[r];
            v = fmaxf(v, __shfl_xor_sync(0xffffffffu, v, 1));
            v = fmaxf(v, __shfl_xor_sync(0xffffffffu, v, 2));
            mloc[r] = v;
        }
        float alpha[4];
        #pragma unroll
        for (int r = 0; r < 4; r++) {
            float mn = fmaxf(m_run[r], mloc[r]);
            alpha[r] = __expf(m_run[r] - mn);
            m_run[r] = mn;
            l_run[r] *= alpha[r];
        }
        float lsum[4] = {0.f, 0.f, 0.f, 0.f};
        #pragma unroll
        for (int mt = 0; mt < 2; mt++)
            #pragma unroll
            for (int nt = 0; nt < 8; nt++) {
                float p0 = __expf(sc[mt][nt][0] - m_run[2*mt]);
                float p1 = __expf(sc[mt][nt][1] - m_run[2*mt]);
                float p2 = __expf(sc[mt][nt][2] - m_run[2*mt+1]);
                float p3 = __expf(sc[mt][nt][3] - m_run[2*mt+1]);
                lsum[2*mt]   += p0 + p1;
                lsum[2*mt+1] += p2 + p3;
                pwu[(mt*16 + lg)*36     + nt*4 + lq] = packh2(p0, p1);
                pwu[(mt*16 + lg + 8)*36 + nt*4 + lq] = packh2(p2, p3);
            }
        #pragma unroll
        for (int r = 0; r < 4; r++) {
            float v = lsum[r];
            v += __shfl_xor_sync(0xffffffffu, v, 1);
            v += __shfl_xor_sync(0xffffffffu, v, 2);
            l_run[r] += v;
        }
        #pragma unroll
        for (int mt = 0; mt < 2; mt++)
            #pragma unroll
            for (int nt = 0; nt < 8; nt++) {
                O[mt][nt][0] *= alpha[2*mt];
                O[mt][nt][1] *= alpha[2*mt];
                O[mt][nt][2] *= alpha[2*mt+1];
                O[mt][nt][3] *= alpha[2*mt+1];
            }
        __syncwarp();

        // ---- PV (fp16, 4 k16 chunks over 64 keys) ----
        #pragma unroll
        for (int kk = 0; kk < 4; kk++) {
            uint32_t pa[2][4];
            #pragma unroll
            for (int mt = 0; mt < 2; mt++) {
                int r0 = mt*16 + lg;
                pa[mt][0] = pwu[r0*36 + kk*8 + lq];
                pa[mt][1] = pwu[(r0+8)*36 + kk*8 + lq];
                pa[mt][2] = pwu[r0*36 + kk*8 + lq + 4];
                pa[mt][3] = pwu[(r0+8)*36 + kk*8 + lq + 4];
            }
            #pragma unroll
            for (int nt = 0; nt < 8; nt++) {
                int n0 = nt*8 + lg;
                uint32_t b0 = VH[n0*36 + kk*8 + lq];
                uint32_t b1 = VH[n0*36 + kk*8 + lq + 4];
                #pragma unroll
                for (int mt = 0; mt < 2; mt++)
                    mmaf16(O[mt][nt], pa[mt], b0, b1);
            }
        }
        // no end-of-loop sync: top-of-loop __syncthreads orders buffer reuse
    }

    // ---- write output ----
    #pragma unroll
    for (int mt = 0; mt < 2; mt++)
        #pragma unroll
        for (int half_ = 0; half_ < 2; half_++) {
            int row = qt*128 + wid*32 + mt*16 + lg + half_*8;
            float inv = 1.f / l_run[2*mt + half_];
            float* op = out + ((size_t)(b*SEQ + row)) * (NH*VL) + h*VL;
            #pragma unroll
            for (int nt = 0; nt < 8; nt++)
                *(float2*)&op[nt*8 + 2*lq] = make_float2(O[mt][nt][2*half_]*inv,
                                                         O[mt][nt][2*half_+1]*inv);
        }
}

// ---------------------------------------------------------------------------
extern "C" void kernel_launch(void* const* d_in, const int* in_sizes, int n_in,
                              void* d_out, int out_size) {
    const float* x   = (const float*)d_in[0];
    const float* Wq  = (const float*)d_in[1];
    const float* bq  = (const float*)d_in[2];
    const float* Wqc = (const float*)d_in[3];
    const float* bqc = (const float*)d_in[4];
    const float* Wk  = (const float*)d_in[5];
    const float* bk  = (const float*)d_in[6];
    const float* Wkc = (const float*)d_in[7];
    const float* bkc = (const float*)d_in[8];
    const float* Wv  = (const float*)d_in[9];
    const float* bv  = (const float*)d_in[10];
    const float* Wvc = (const float*)d_in[11];
    const float* bvc = (const float*)d_in[12];
    float* out = (float*)d_out;

    static bool attr_set = false;
    if (!attr_set) {
        cudaFuncSetAttribute(attn_mma, cudaFuncAttributeMaxDynamicSharedMemorySize, SA_TOT * 4);
        cudaFuncSetAttribute(gemm_mma, cudaFuncAttributeMaxDynamicSharedMemorySize, GSM_BYTES);
        attr_set = true;
    }

    prep<<<7500, 256>>>(x, Wq, bq, Wqc, bqc, Wk, bk, Wkc, bkc, Wv, bv, Wvc, bvc);

    gemm_mma<<<dim3(NTOT/128, MROWS/128), 256, GSM_BYTES>>>();

    attn_mma<<<dim3(SEQ/128, NH, BATCH), 128, SA_TOT * 4>>>(out);
}